// round 15
// baseline (speedup 1.0000x reference)
#include <cuda_runtime.h>
#include <math.h>
#include <limits.h>

#define HDIM 128
#define SDIM 32
#define KTOP 8
#define RPB  128                  // rows per K1 block
#define NBLK 782                  // ceil(100000/128)
#define NCAND (NBLK * KTOP)       // 6256

// Scratch (__device__ globals; no allocation allowed)
__device__ float2 g_cand[8192];   // (value, index bits); NCAND used, padded

__device__ __forceinline__ bool better(float va, int ia, float vb, int ib) {
    // jax.lax.top_k ordering: higher value first, ties -> lower index
    return (va > vb) || (va == vb && ia < ib);
}

__device__ __forceinline__ void ce(float& va, int& ia, float& vb, int& ib) {
    if (better(vb, ib, va, ia)) {
        float tv = va; va = vb; vb = tv;
        int   ti = ia; ia = ib; ib = ti;
    }
}

// Merge two sorted-descending 8-lists -> top-8 of union (register bitonic).
__device__ __forceinline__ void merge8(float* lv, int* li,
                                       const float* pv, const int* pi) {
    float mv[8]; int mi[8];
#pragma unroll
    for (int i = 0; i < 8; ++i) {
        if (better(lv[i], li[i], pv[7 - i], pi[7 - i])) { mv[i] = lv[i]; mi[i] = li[i]; }
        else                                            { mv[i] = pv[7 - i]; mi[i] = pi[7 - i]; }
    }
    ce(mv[0], mi[0], mv[4], mi[4]); ce(mv[1], mi[1], mv[5], mi[5]);
    ce(mv[2], mi[2], mv[6], mi[6]); ce(mv[3], mi[3], mv[7], mi[7]);
    ce(mv[0], mi[0], mv[2], mi[2]); ce(mv[1], mi[1], mv[3], mi[3]);
    ce(mv[4], mi[4], mv[6], mi[6]); ce(mv[5], mi[5], mv[7], mi[7]);
    ce(mv[0], mi[0], mv[1], mi[1]); ce(mv[2], mi[2], mv[3], mi[3]);
    ce(mv[4], mi[4], mv[5], mi[5]); ce(mv[6], mi[6], mv[7], mi[7]);
#pragma unroll
    for (int i = 0; i < 8; ++i) { lv[i] = mv[i]; li[i] = mi[i]; }
}

template <int MAXOFF>
__device__ __forceinline__ void warp_merge_levels(float* lv, int* li) {
#pragma unroll
    for (int o = 1; o <= MAXOFF; o <<= 1) {
        float pv[8]; int pi[8];
#pragma unroll
        for (int j = 0; j < 8; ++j) {
            pv[j] = __shfl_xor_sync(0xffffffffu, lv[j], o);
            pi[j] = __shfl_xor_sync(0xffffffffu, li[j], o);
        }
        merge8(lv, li, pv, pi);
    }
}

__device__ __forceinline__ void insert_topk(float* lv, int* li, float v, int c) {
    if (better(v, c, lv[KTOP - 1], li[KTOP - 1])) {
        int j = KTOP - 1;
#pragma unroll
        for (; j > 0; --j) {
            if (better(v, c, lv[j - 1], li[j - 1])) {
                lv[j] = lv[j - 1];
                li[j] = li[j - 1];
            } else break;
        }
        lv[j] = v;
        li[j] = c;
    }
}

// ---------------------------------------------------------------------------
// K1: cosine sims (coalesced warp-per-row, 16 rows/warp) + block top-8.
// Proven R8 structure (~11us). Fence-free; kernel boundary orders stores.
// ---------------------------------------------------------------------------
__global__ void __launch_bounds__(256)
sims_topk(const float* __restrict__ q,
          const float* __restrict__ emb,
          int C) {
    __shared__ float sq[HDIM];
    __shared__ float s_rqn;
    __shared__ float s_sims[RPB];
    __shared__ float sv[16 * KTOP];
    __shared__ int   si[16 * KTOP];

    const int t    = threadIdx.x;
    const int lane = t & 31;
    const int w    = t >> 5;

    if (t < HDIM) sq[t] = q[t];               // query row 0
    __syncthreads();
    if (t < 32) {
        const float4 a = reinterpret_cast<const float4*>(sq)[t];
        float s = a.x * a.x + a.y * a.y + a.z * a.z + a.w * a.w;
#pragma unroll
        for (int o = 16; o; o >>= 1) s += __shfl_xor_sync(0xffffffffu, s, o);
        if (t == 0) s_rqn = 1.0f / fmaxf(sqrtf(s), 1e-8f);
    }
    __syncthreads();
    const float rqn = s_rqn;
    const float4 q4 = reinterpret_cast<const float4*>(sq)[lane];

    const float4* __restrict__ emb4 = reinterpret_cast<const float4*>(emb);
    const int base = blockIdx.x * RPB;

#pragma unroll
    for (int it = 0; it < 4; ++it) {
        const int loc0 = w * 16 + it * 4;
        float4 ev[4];
#pragma unroll
        for (int j = 0; j < 4; ++j) {
            const int r = min(base + loc0 + j, C - 1);
            ev[j] = emb4[(size_t)r * (HDIM / 4) + lane];
        }
        float dot[4], esq[4];
#pragma unroll
        for (int j = 0; j < 4; ++j) {
            dot[j] = ev[j].x * q4.x + ev[j].y * q4.y + ev[j].z * q4.z + ev[j].w * q4.w;
            esq[j] = ev[j].x * ev[j].x + ev[j].y * ev[j].y + ev[j].z * ev[j].z + ev[j].w * ev[j].w;
        }
#pragma unroll
        for (int o = 16; o; o >>= 1) {
#pragma unroll
            for (int j = 0; j < 4; ++j) {
                dot[j] += __shfl_xor_sync(0xffffffffu, dot[j], o);
                esq[j] += __shfl_xor_sync(0xffffffffu, esq[j], o);
            }
        }
        if (lane < 4) {
            const int r = base + loc0 + lane;
            s_sims[loc0 + lane] = (r < C)
                ? dot[lane] * rqn / fmaxf(sqrtf(esq[lane]), 1e-8f)
                : -INFINITY;
        }
    }
    __syncthreads();

    // Block top-8 of 128 sims: 16 threads x 8 inserts, then 4-level merge.
    if (t < 16) {
        float lv[KTOP]; int li[KTOP];
#pragma unroll
        for (int j = 0; j < KTOP; ++j) { lv[j] = -INFINITY; li[j] = INT_MAX; }
#pragma unroll
        for (int j = 0; j < 8; ++j)
            insert_topk(lv, li, s_sims[t * 8 + j], base + t * 8 + j);
#pragma unroll
        for (int j = 0; j < KTOP; ++j) { sv[t * KTOP + j] = lv[j]; si[t * KTOP + j] = li[j]; }
    }
    __syncthreads();
    for (int s = 8; s > 0; s >>= 1) {
        if (t < s) {
            float mv[KTOP]; int mi[KTOP];
            int a = 0, b = 0;
#pragma unroll
            for (int j = 0; j < KTOP; ++j) {
                const float va = sv[t * KTOP + a];       const int ia = si[t * KTOP + a];
                const float vb = sv[(t + s) * KTOP + b]; const int ib = si[(t + s) * KTOP + b];
                if (better(va, ia, vb, ib)) { mv[j] = va; mi[j] = ia; ++a; }
                else                        { mv[j] = vb; mi[j] = ib; ++b; }
            }
#pragma unroll
            for (int j = 0; j < KTOP; ++j) { sv[t * KTOP + j] = mv[j]; si[t * KTOP + j] = mi[j]; }
        }
        __syncthreads();
    }
    if (t < KTOP)
        g_cand[blockIdx.x * KTOP + t] = make_float2(sv[t], __int_as_float(si[t]));
}

// ---------------------------------------------------------------------------
// K2 (PDL): 64 blocks. Every block redundantly merges all candidates to the
// global top-8 (front-batched loads + register bitonic), then gathers its
// 1/64 slice of the episodes. Block 0 writes the scores.
// ---------------------------------------------------------------------------
__global__ void __launch_bounds__(256)
final_gather(const float* __restrict__ episodes,
             float* __restrict__ out) {
    __shared__ float swv[8 * KTOP];
    __shared__ int   swi[8 * KTOP];
    __shared__ float s_tv[KTOP];
    __shared__ int   s_ti[KTOP];

    const int t    = threadIdx.x;
    const int lane = t & 31;
    const int w    = t >> 5;

    cudaGridDependencySynchronize();          // wait for K1's candidates

    // Per-thread top-8 of 32 strided candidates: 4 waves of 8 front-batched
    // LDG.64 (padded region reads -inf? no: clamp address, patch value).
    float lv[KTOP]; int li[KTOP];
#pragma unroll
    for (int j = 0; j < KTOP; ++j) { lv[j] = -INFINITY; li[j] = INT_MAX; }
#pragma unroll
    for (int wv = 0; wv < 4; ++wv) {
        float2 cd[8];
#pragma unroll
        for (int i = 0; i < 8; ++i) {
            const int c = (wv * 8 + i) * 256 + t;      // 0..8191
            cd[i] = g_cand[min(c, NCAND - 1)];
            if (c >= NCAND) cd[i] = make_float2(-INFINITY, __int_as_float(INT_MAX));
        }
#pragma unroll
        for (int i = 0; i < 8; ++i)
            insert_topk(lv, li, cd[i].x, __float_as_int(cd[i].y));
    }

    warp_merge_levels<16>(lv, li);            // 5 shfl levels -> warp top-8
    if (lane == 0) {
#pragma unroll
        for (int j = 0; j < KTOP; ++j) { swv[w * KTOP + j] = lv[j]; swi[w * KTOP + j] = li[j]; }
    }
    __syncthreads();
    if (t < 32) {
        float fv[KTOP]; int fi[KTOP];
        if (lane < 8) {
#pragma unroll
            for (int j = 0; j < KTOP; ++j) { fv[j] = swv[lane * KTOP + j]; fi[j] = swi[lane * KTOP + j]; }
        } else {
#pragma unroll
            for (int j = 0; j < KTOP; ++j) { fv[j] = -INFINITY; fi[j] = INT_MAX; }
        }
        warp_merge_levels<4>(fv, fi);          // 3 shfl levels -> global top-8
        if (lane == 0) {
#pragma unroll
            for (int j = 0; j < KTOP; ++j) { s_tv[j] = fv[j]; s_ti[j] = fi[j]; }
        }
    }
    __syncthreads();

    // Gather: block b copies episode e = b>>3, part = b&7 (128 float4).
    const int e    = blockIdx.x >> 3;
    const int part = blockIdx.x & 7;
    const int idx  = s_ti[e];
    const int per  = (SDIM * HDIM / 4) / 8;    // 128 float4
    const float4* __restrict__ src =
        reinterpret_cast<const float4*>(episodes + (size_t)idx * (SDIM * HDIM)) + part * per;
    float4* __restrict__ dst =
        reinterpret_cast<float4*>(out + (size_t)e * (SDIM * HDIM)) + part * per;
    if (t < per) dst[t] = src[t];

    if (blockIdx.x == 0 && t < KTOP)
        out[KTOP * SDIM * HDIM + t] = s_tv[t]; // top_scores[0]
}

// PDL launch: pre-launch while predecessor runs; in-kernel
// cudaGridDependencySynchronize provides the data dependency.
template <typename... Args>
static void launch_pdl(void (*kern)(Args...), dim3 grid, dim3 block, Args... args) {
    cudaLaunchConfig_t cfg = {};
    cfg.gridDim  = grid;
    cfg.blockDim = block;
    cfg.dynamicSmemBytes = 0;
    cfg.stream = 0;
    cudaLaunchAttribute attr[1];
    attr[0].id = cudaLaunchAttributeProgrammaticStreamSerialization;
    attr[0].val.programmaticStreamSerializationAllowed = 1;
    cfg.attrs = attr;
    cfg.numAttrs = 1;
    cudaLaunchKernelEx(&cfg, kern, args...);
}

extern "C" void kernel_launch(void* const* d_in, const int* in_sizes, int n_in,
                              void* d_out, int out_size) {
    const float* query    = (const float*)d_in[0];  // [B, 128]
    const float* episodes = (const float*)d_in[1];  // [C, 32, 128]
    const float* emb      = (const float*)d_in[2];  // [C, 128]
    (void)n_in; (void)out_size;

    const int C    = in_sizes[2] / HDIM;            // 100000
    const int nblk = (C + RPB - 1) / RPB;           // 782 == NBLK

    sims_topk<<<nblk, 256>>>(query, emb, C);
    launch_pdl(final_gather, dim3(64), dim3(256),
               (const float*)episodes, (float*)d_out);
}

// round 16
// speedup vs baseline: 1.0580x; 1.0580x over previous
#include <cuda_runtime.h>
#include <math.h>
#include <limits.h>

#define HDIM 128
#define SDIM 32
#define KTOP 8
#define RPB  128                  // rows per K1 block
#define NBLK 782                  // ceil(100000/128)
#define NCAND (NBLK * KTOP)       // 6256

// Scratch (__device__ globals; no allocation allowed)
__device__ float2 g_cand[NCAND];  // (value, index bits)

__device__ __forceinline__ bool better(float va, int ia, float vb, int ib) {
    // jax.lax.top_k ordering: higher value first, ties -> lower index
    return (va > vb) || (va == vb && ia < ib);
}

__device__ __forceinline__ void ce(float& va, int& ia, float& vb, int& ib) {
    if (better(vb, ib, va, ia)) {
        float tv = va; va = vb; vb = tv;
        int   ti = ia; ia = ib; ib = ti;
    }
}

// Merge two sorted-descending 8-lists -> top-8 of union (register bitonic).
__device__ __forceinline__ void merge8(float* lv, int* li,
                                       const float* pv, const int* pi) {
    float mv[8]; int mi[8];
#pragma unroll
    for (int i = 0; i < 8; ++i) {
        if (better(lv[i], li[i], pv[7 - i], pi[7 - i])) { mv[i] = lv[i]; mi[i] = li[i]; }
        else                                            { mv[i] = pv[7 - i]; mi[i] = pi[7 - i]; }
    }
    ce(mv[0], mi[0], mv[4], mi[4]); ce(mv[1], mi[1], mv[5], mi[5]);
    ce(mv[2], mi[2], mv[6], mi[6]); ce(mv[3], mi[3], mv[7], mi[7]);
    ce(mv[0], mi[0], mv[2], mi[2]); ce(mv[1], mi[1], mv[3], mi[3]);
    ce(mv[4], mi[4], mv[6], mi[6]); ce(mv[5], mi[5], mv[7], mi[7]);
    ce(mv[0], mi[0], mv[1], mi[1]); ce(mv[2], mi[2], mv[3], mi[3]);
    ce(mv[4], mi[4], mv[5], mi[5]); ce(mv[6], mi[6], mv[7], mi[7]);
#pragma unroll
    for (int i = 0; i < 8; ++i) { lv[i] = mv[i]; li[i] = mi[i]; }
}

template <int MAXOFF>
__device__ __forceinline__ void warp_merge_levels(float* lv, int* li) {
#pragma unroll
    for (int o = 1; o <= MAXOFF; o <<= 1) {
        float pv[8]; int pi[8];
#pragma unroll
        for (int j = 0; j < 8; ++j) {
            pv[j] = __shfl_xor_sync(0xffffffffu, lv[j], o);
            pi[j] = __shfl_xor_sync(0xffffffffu, li[j], o);
        }
        merge8(lv, li, pv, pi);
    }
}

__device__ __forceinline__ void insert_topk(float* lv, int* li, float v, int c) {
    if (better(v, c, lv[KTOP - 1], li[KTOP - 1])) {
        int j = KTOP - 1;
#pragma unroll
        for (; j > 0; --j) {
            if (better(v, c, lv[j - 1], li[j - 1])) {
                lv[j] = lv[j - 1];
                li[j] = li[j - 1];
            } else break;
        }
        lv[j] = v;
        li[j] = c;
    }
}

// ---------------------------------------------------------------------------
// K1: cosine sims (coalesced warp-per-row, 16 rows/warp) + block top-8.
// Measured ~11.4us in R8/R15. Early PDL trigger after candidate stores.
// ---------------------------------------------------------------------------
__global__ void __launch_bounds__(256)
sims_topk(const float* __restrict__ q,
          const float* __restrict__ emb,
          int C) {
    __shared__ float sq[HDIM];
    __shared__ float s_rqn;
    __shared__ float s_sims[RPB];
    __shared__ float sv[16 * KTOP];
    __shared__ int   si[16 * KTOP];

    const int t    = threadIdx.x;
    const int lane = t & 31;
    const int w    = t >> 5;

    if (t < HDIM) sq[t] = q[t];               // query row 0
    __syncthreads();
    if (t < 32) {
        const float4 a = reinterpret_cast<const float4*>(sq)[t];
        float s = a.x * a.x + a.y * a.y + a.z * a.z + a.w * a.w;
#pragma unroll
        for (int o = 16; o; o >>= 1) s += __shfl_xor_sync(0xffffffffu, s, o);
        if (t == 0) s_rqn = 1.0f / fmaxf(sqrtf(s), 1e-8f);
    }
    __syncthreads();
    const float rqn = s_rqn;
    const float4 q4 = reinterpret_cast<const float4*>(sq)[lane];

    const float4* __restrict__ emb4 = reinterpret_cast<const float4*>(emb);
    const int base = blockIdx.x * RPB;

#pragma unroll
    for (int it = 0; it < 4; ++it) {
        const int loc0 = w * 16 + it * 4;
        float4 ev[4];
#pragma unroll
        for (int j = 0; j < 4; ++j) {
            const int r = min(base + loc0 + j, C - 1);
            ev[j] = emb4[(size_t)r * (HDIM / 4) + lane];
        }
        float dot[4], esq[4];
#pragma unroll
        for (int j = 0; j < 4; ++j) {
            dot[j] = ev[j].x * q4.x + ev[j].y * q4.y + ev[j].z * q4.z + ev[j].w * q4.w;
            esq[j] = ev[j].x * ev[j].x + ev[j].y * ev[j].y + ev[j].z * ev[j].z + ev[j].w * ev[j].w;
        }
#pragma unroll
        for (int o = 16; o; o >>= 1) {
#pragma unroll
            for (int j = 0; j < 4; ++j) {
                dot[j] += __shfl_xor_sync(0xffffffffu, dot[j], o);
                esq[j] += __shfl_xor_sync(0xffffffffu, esq[j], o);
            }
        }
        if (lane < 4) {
            const int r = base + loc0 + lane;
            s_sims[loc0 + lane] = (r < C)
                ? dot[lane] * rqn / fmaxf(sqrtf(esq[lane]), 1e-8f)
                : -INFINITY;
        }
    }
    __syncthreads();

    // Block top-8 of 128 sims: 16 threads x 8 inserts, then 4-level merge.
    if (t < 16) {
        float lv[KTOP]; int li[KTOP];
#pragma unroll
        for (int j = 0; j < KTOP; ++j) { lv[j] = -INFINITY; li[j] = INT_MAX; }
#pragma unroll
        for (int j = 0; j < 8; ++j)
            insert_topk(lv, li, s_sims[t * 8 + j], base + t * 8 + j);
#pragma unroll
        for (int j = 0; j < KTOP; ++j) { sv[t * KTOP + j] = lv[j]; si[t * KTOP + j] = li[j]; }
    }
    __syncthreads();
    for (int s = 8; s > 0; s >>= 1) {
        if (t < s) {
            float mv[KTOP]; int mi[KTOP];
            int a = 0, b = 0;
#pragma unroll
            for (int j = 0; j < KTOP; ++j) {
                const float va = sv[t * KTOP + a];       const int ia = si[t * KTOP + a];
                const float vb = sv[(t + s) * KTOP + b]; const int ib = si[(t + s) * KTOP + b];
                if (better(va, ia, vb, ib)) { mv[j] = va; mi[j] = ia; ++a; }
                else                        { mv[j] = vb; mi[j] = ib; ++b; }
            }
#pragma unroll
            for (int j = 0; j < KTOP; ++j) { sv[t * KTOP + j] = mv[j]; si[t * KTOP + j] = mi[j]; }
        }
        __syncthreads();
    }
    if (t < KTOP)
        g_cand[blockIdx.x * KTOP + t] = make_float2(sv[t], __int_as_float(si[t]));
    __syncthreads();
    cudaTriggerProgrammaticLaunchCompletion();  // release K2 before teardown
}

// ---------------------------------------------------------------------------
// K2 (PDL): one 1024-thread block. 7 front-batched candidate loads/thread,
// register-bitonic reduce to global top-8, then front-batched gather.
// ---------------------------------------------------------------------------
__global__ void __launch_bounds__(1024)
final_gather(const float* __restrict__ episodes,
             float* __restrict__ out) {
    __shared__ float swv[32 * KTOP];
    __shared__ int   swi[32 * KTOP];
    __shared__ float s_tv[KTOP];
    __shared__ int   s_ti[KTOP];

    const int t    = threadIdx.x;
    const int lane = t & 31;
    const int w    = t >> 5;

    cudaGridDependencySynchronize();          // wait for K1's candidates

    // 7 unconditional front-batched LDG.64 (clamped addr, patched value).
    float2 cd[7];
#pragma unroll
    for (int r = 0; r < 7; ++r) {
        const int c = t + r * 1024;
        cd[r] = g_cand[min(c, NCAND - 1)];
        if (c >= NCAND) cd[r] = make_float2(-INFINITY, __int_as_float(INT_MAX));
    }
    float lv[KTOP]; int li[KTOP];
#pragma unroll
    for (int j = 0; j < KTOP; ++j) { lv[j] = -INFINITY; li[j] = INT_MAX; }
#pragma unroll
    for (int r = 0; r < 7; ++r)
        insert_topk(lv, li, cd[r].x, __float_as_int(cd[r].y));

    warp_merge_levels<16>(lv, li);            // 5 shfl levels -> warp top-8
    if (lane == 0) {
#pragma unroll
        for (int j = 0; j < KTOP; ++j) { swv[w * KTOP + j] = lv[j]; swi[w * KTOP + j] = li[j]; }
    }
    __syncthreads();

    if (t < 32) {
        // lane takes warp-list `lane`; one 5-level bitonic over 32 lists.
        float fv[KTOP]; int fi[KTOP];
#pragma unroll
        for (int j = 0; j < KTOP; ++j) { fv[j] = swv[lane * KTOP + j]; fi[j] = swi[lane * KTOP + j]; }
        warp_merge_levels<16>(fv, fi);
        if (lane == 0) {
#pragma unroll
            for (int j = 0; j < KTOP; ++j) { s_tv[j] = fv[j]; s_ti[j] = fi[j]; }
        }
    }
    __syncthreads();

    // Gather 8 episodes [8,32,128]: thread t = float4 column t of each
    // episode; 8 independent front-batched loads, then 8 stores.
    int idx[KTOP];
#pragma unroll
    for (int e = 0; e < KTOP; ++e) idx[e] = s_ti[e];

    const float4* __restrict__ epi4 = reinterpret_cast<const float4*>(episodes);
    float4* __restrict__ out4 = reinterpret_cast<float4*>(out);
    const int EP4 = SDIM * HDIM / 4;           // 1024 float4 per episode
    float4 vals[KTOP];
#pragma unroll
    for (int e = 0; e < KTOP; ++e)
        vals[e] = epi4[(size_t)idx[e] * EP4 + t];
#pragma unroll
    for (int e = 0; e < KTOP; ++e)
        out4[e * EP4 + t] = vals[e];

    if (t < KTOP)
        out[KTOP * SDIM * HDIM + t] = s_tv[t]; // top_scores[0]
}

// PDL launch: pre-launch while predecessor runs; in-kernel
// cudaGridDependencySynchronize provides the data dependency.
template <typename... Args>
static void launch_pdl(void (*kern)(Args...), dim3 grid, dim3 block, Args... args) {
    cudaLaunchConfig_t cfg = {};
    cfg.gridDim  = grid;
    cfg.blockDim = block;
    cfg.dynamicSmemBytes = 0;
    cfg.stream = 0;
    cudaLaunchAttribute attr[1];
    attr[0].id = cudaLaunchAttributeProgrammaticStreamSerialization;
    attr[0].val.programmaticStreamSerializationAllowed = 1;
    cfg.attrs = attr;
    cfg.numAttrs = 1;
    cudaLaunchKernelEx(&cfg, kern, args...);
}

extern "C" void kernel_launch(void* const* d_in, const int* in_sizes, int n_in,
                              void* d_out, int out_size) {
    const float* query    = (const float*)d_in[0];  // [B, 128]
    const float* episodes = (const float*)d_in[1];  // [C, 32, 128]
    const float* emb      = (const float*)d_in[2];  // [C, 128]
    (void)n_in; (void)out_size;

    const int C    = in_sizes[2] / HDIM;            // 100000
    const int nblk = (C + RPB - 1) / RPB;           // 782 == NBLK

    sims_topk<<<nblk, 256>>>(query, emb, C);
    launch_pdl(final_gather, dim3(1), dim3(1024),
               (const float*)episodes, (float*)d_out);
}

// round 17
// speedup vs baseline: 1.1146x; 1.0535x over previous
#include <cuda_runtime.h>
#include <math.h>
#include <limits.h>

#define HDIM 128
#define SDIM 32
#define KTOP 8
#define RPB  128                  // rows per K1 block
#define NBLK 782                  // ceil(100000/128)
#define NCAND (NBLK * KTOP)       // 6256

// Scratch (__device__ globals; no allocation allowed)
__device__ float2 g_cand[NCAND];  // (value, index bits)
__device__ float  g_top_v[KTOP];
__device__ int    g_top_i[KTOP];

__device__ __forceinline__ bool better(float va, int ia, float vb, int ib) {
    // jax.lax.top_k ordering: higher value first, ties -> lower index
    return (va > vb) || (va == vb && ia < ib);
}

__device__ __forceinline__ void ce(float& va, int& ia, float& vb, int& ib) {
    if (better(vb, ib, va, ia)) {
        float tv = va; va = vb; vb = tv;
        int   ti = ia; ia = ib; ib = ti;
    }
}

// Merge two sorted-descending 8-lists -> top-8 of union (register bitonic).
__device__ __forceinline__ void merge8(float* lv, int* li,
                                       const float* pv, const int* pi) {
    float mv[8]; int mi[8];
#pragma unroll
    for (int i = 0; i < 8; ++i) {
        if (better(lv[i], li[i], pv[7 - i], pi[7 - i])) { mv[i] = lv[i]; mi[i] = li[i]; }
        else                                            { mv[i] = pv[7 - i]; mi[i] = pi[7 - i]; }
    }
    ce(mv[0], mi[0], mv[4], mi[4]); ce(mv[1], mi[1], mv[5], mi[5]);
    ce(mv[2], mi[2], mv[6], mi[6]); ce(mv[3], mi[3], mv[7], mi[7]);
    ce(mv[0], mi[0], mv[2], mi[2]); ce(mv[1], mi[1], mv[3], mi[3]);
    ce(mv[4], mi[4], mv[6], mi[6]); ce(mv[5], mi[5], mv[7], mi[7]);
    ce(mv[0], mi[0], mv[1], mi[1]); ce(mv[2], mi[2], mv[3], mi[3]);
    ce(mv[4], mi[4], mv[5], mi[5]); ce(mv[6], mi[6], mv[7], mi[7]);
#pragma unroll
    for (int i = 0; i < 8; ++i) { lv[i] = mv[i]; li[i] = mi[i]; }
}

template <int MAXOFF>
__device__ __forceinline__ void warp_merge_levels(float* lv, int* li) {
#pragma unroll
    for (int o = 1; o <= MAXOFF; o <<= 1) {
        float pv[8]; int pi[8];
#pragma unroll
        for (int j = 0; j < 8; ++j) {
            pv[j] = __shfl_xor_sync(0xffffffffu, lv[j], o);
            pi[j] = __shfl_xor_sync(0xffffffffu, li[j], o);
        }
        merge8(lv, li, pv, pi);
    }
}

__device__ __forceinline__ void insert_topk(float* lv, int* li, float v, int c) {
    if (better(v, c, lv[KTOP - 1], li[KTOP - 1])) {
        int j = KTOP - 1;
#pragma unroll
        for (; j > 0; --j) {
            if (better(v, c, lv[j - 1], li[j - 1])) {
                lv[j] = lv[j - 1];
                li[j] = li[j - 1];
            } else break;
        }
        lv[j] = v;
        li[j] = c;
    }
}

// ---------------------------------------------------------------------------
// K1: cosine sims (coalesced warp-per-row, 16 rows/warp) + block top-8.
// Measured ~11us. Early PDL trigger after candidate stores.
// ---------------------------------------------------------------------------
__global__ void __launch_bounds__(256)
sims_topk(const float* __restrict__ q,
          const float* __restrict__ emb,
          int C) {
    __shared__ float sq[HDIM];
    __shared__ float s_rqn;
    __shared__ float s_sims[RPB];
    __shared__ float sv[16 * KTOP];
    __shared__ int   si[16 * KTOP];

    const int t    = threadIdx.x;
    const int lane = t & 31;
    const int w    = t >> 5;

    if (t < HDIM) sq[t] = q[t];               // query row 0
    __syncthreads();
    if (t < 32) {
        const float4 a = reinterpret_cast<const float4*>(sq)[t];
        float s = a.x * a.x + a.y * a.y + a.z * a.z + a.w * a.w;
#pragma unroll
        for (int o = 16; o; o >>= 1) s += __shfl_xor_sync(0xffffffffu, s, o);
        if (t == 0) s_rqn = 1.0f / fmaxf(sqrtf(s), 1e-8f);
    }
    __syncthreads();
    const float rqn = s_rqn;
    const float4 q4 = reinterpret_cast<const float4*>(sq)[lane];

    const float4* __restrict__ emb4 = reinterpret_cast<const float4*>(emb);
    const int base = blockIdx.x * RPB;

#pragma unroll
    for (int it = 0; it < 4; ++it) {
        const int loc0 = w * 16 + it * 4;
        float4 ev[4];
#pragma unroll
        for (int j = 0; j < 4; ++j) {
            const int r = min(base + loc0 + j, C - 1);
            ev[j] = emb4[(size_t)r * (HDIM / 4) + lane];
        }
        float dot[4], esq[4];
#pragma unroll
        for (int j = 0; j < 4; ++j) {
            dot[j] = ev[j].x * q4.x + ev[j].y * q4.y + ev[j].z * q4.z + ev[j].w * q4.w;
            esq[j] = ev[j].x * ev[j].x + ev[j].y * ev[j].y + ev[j].z * ev[j].z + ev[j].w * ev[j].w;
        }
#pragma unroll
        for (int o = 16; o; o >>= 1) {
#pragma unroll
            for (int j = 0; j < 4; ++j) {
                dot[j] += __shfl_xor_sync(0xffffffffu, dot[j], o);
                esq[j] += __shfl_xor_sync(0xffffffffu, esq[j], o);
            }
        }
        if (lane < 4) {
            const int r = base + loc0 + lane;
            s_sims[loc0 + lane] = (r < C)
                ? dot[lane] * rqn / fmaxf(sqrtf(esq[lane]), 1e-8f)
                : -INFINITY;
        }
    }
    __syncthreads();

    // Block top-8 of 128 sims: 16 threads x 8 inserts, then 4-level merge.
    if (t < 16) {
        float lv[KTOP]; int li[KTOP];
#pragma unroll
        for (int j = 0; j < KTOP; ++j) { lv[j] = -INFINITY; li[j] = INT_MAX; }
#pragma unroll
        for (int j = 0; j < 8; ++j)
            insert_topk(lv, li, s_sims[t * 8 + j], base + t * 8 + j);
#pragma unroll
        for (int j = 0; j < KTOP; ++j) { sv[t * KTOP + j] = lv[j]; si[t * KTOP + j] = li[j]; }
    }
    __syncthreads();
    for (int s = 8; s > 0; s >>= 1) {
        if (t < s) {
            float mv[KTOP]; int mi[KTOP];
            int a = 0, b = 0;
#pragma unroll
            for (int j = 0; j < KTOP; ++j) {
                const float va = sv[t * KTOP + a];       const int ia = si[t * KTOP + a];
                const float vb = sv[(t + s) * KTOP + b]; const int ib = si[(t + s) * KTOP + b];
                if (better(va, ia, vb, ib)) { mv[j] = va; mi[j] = ia; ++a; }
                else                        { mv[j] = vb; mi[j] = ib; ++b; }
            }
#pragma unroll
            for (int j = 0; j < KTOP; ++j) { sv[t * KTOP + j] = mv[j]; si[t * KTOP + j] = mi[j]; }
        }
        __syncthreads();
    }
    if (t < KTOP)
        g_cand[blockIdx.x * KTOP + t] = make_float2(sv[t], __int_as_float(si[t]));
    __syncthreads();
    cudaTriggerProgrammaticLaunchCompletion();
}

// ---------------------------------------------------------------------------
// K2 (PDL): 1024 threads merge 6256 candidates -> global top-8 + scores.
// 7 front-batched LDG.64 per thread; register-bitonic reduce.
// ---------------------------------------------------------------------------
__global__ void __launch_bounds__(1024)
topk_final(float* __restrict__ out) {
    __shared__ float swv[32 * KTOP];
    __shared__ int   swi[32 * KTOP];

    const int t    = threadIdx.x;
    const int lane = t & 31;
    const int w    = t >> 5;

    cudaGridDependencySynchronize();          // wait for K1's candidates

    float2 cd[7];
#pragma unroll
    for (int r = 0; r < 7; ++r) {
        const int c = t + r * 1024;
        cd[r] = g_cand[min(c, NCAND - 1)];
        if (c >= NCAND) cd[r] = make_float2(-INFINITY, __int_as_float(INT_MAX));
    }
    float lv[KTOP]; int li[KTOP];
#pragma unroll
    for (int j = 0; j < KTOP; ++j) { lv[j] = -INFINITY; li[j] = INT_MAX; }
#pragma unroll
    for (int r = 0; r < 7; ++r)
        insert_topk(lv, li, cd[r].x, __float_as_int(cd[r].y));

    warp_merge_levels<16>(lv, li);            // warp top-8
    if (lane == 0) {
#pragma unroll
        for (int j = 0; j < KTOP; ++j) { swv[w * KTOP + j] = lv[j]; swi[w * KTOP + j] = li[j]; }
    }
    __syncthreads();

    if (t < 32) {
        float fv[KTOP]; int fi[KTOP];
#pragma unroll
        for (int j = 0; j < KTOP; ++j) { fv[j] = swv[lane * KTOP + j]; fi[j] = swi[lane * KTOP + j]; }
        warp_merge_levels<16>(fv, fi);         // 32 lists -> 1
        if (lane == 0) {
#pragma unroll
            for (int j = 0; j < KTOP; ++j) {
                g_top_v[j] = fv[j];
                g_top_i[j] = fi[j];
                out[KTOP * SDIM * HDIM + j] = fv[j];   // top_scores[0]
            }
        }
    }
    cudaTriggerProgrammaticLaunchCompletion();
}

// ---------------------------------------------------------------------------
// K3 (PDL): gather top-8 episodes [8,32,128]; 64 blocks (proven R14 body).
// ---------------------------------------------------------------------------
__global__ void gather_kernel(const float* __restrict__ episodes,
                              float* __restrict__ out) {
    cudaGridDependencySynchronize();          // wait for topk_final's g_top_i

    const int e    = blockIdx.x >> 3;
    const int part = blockIdx.x & 7;
    const int idx  = g_top_i[e];

    const int per = (SDIM * HDIM / 4) / 8;    // 128 float4 per block
    const float4* __restrict__ src =
        reinterpret_cast<const float4*>(episodes + (size_t)idx * (SDIM * HDIM)) + part * per;
    float4* __restrict__ dst =
        reinterpret_cast<float4*>(out + (size_t)e * (SDIM * HDIM)) + part * per;

    if (threadIdx.x < per) dst[threadIdx.x] = src[threadIdx.x];
}

// PDL launch helper.
template <typename... Args>
static void launch_pdl(void (*kern)(Args...), dim3 grid, dim3 block, Args... args) {
    cudaLaunchConfig_t cfg = {};
    cfg.gridDim  = grid;
    cfg.blockDim = block;
    cfg.dynamicSmemBytes = 0;
    cfg.stream = 0;
    cudaLaunchAttribute attr[1];
    attr[0].id = cudaLaunchAttributeProgrammaticStreamSerialization;
    attr[0].val.programmaticStreamSerializationAllowed = 1;
    cfg.attrs = attr;
    cfg.numAttrs = 1;
    cudaLaunchKernelEx(&cfg, kern, args...);
}

extern "C" void kernel_launch(void* const* d_in, const int* in_sizes, int n_in,
                              void* d_out, int out_size) {
    const float* query    = (const float*)d_in[0];  // [B, 128]
    const float* episodes = (const float*)d_in[1];  // [C, 32, 128]
    const float* emb      = (const float*)d_in[2];  // [C, 128]
    (void)n_in; (void)out_size;

    const int C    = in_sizes[2] / HDIM;            // 100000
    const int nblk = (C + RPB - 1) / RPB;           // 782 == NBLK

    sims_topk<<<nblk, 256>>>(query, emb, C);
    launch_pdl(topk_final, dim3(1), dim3(1024), (float*)d_out);
    launch_pdl(gather_kernel, dim3(64), dim3(128),
               (const float*)episodes, (float*)d_out);
}